// round 7
// baseline (speedup 1.0000x reference)
#include <cuda_runtime.h>
#include <cuda_bf16.h>

// SpatialGNN: 2-layer GATv2, G = 6144 graphs, N=32, C=64, H=4, D=16, E=160.
// R7: edge-parallel balanced scoring (no max subtraction -- scores are tiny,
// exp(s)/sum(exp(s)) is shift-invariant), denominator folded into the agg
// loop (no softmax pass, no rden), agg split across lane pairs (shfl combine).

#define Bb 16
#define Cc 64
#define Nn 32
#define Kk 16
#define Ll 24
#define Ee 160
#define Hh 4
#define Dd 16
#define NG 2
#define Mm 64         // GEMM rows = NG * Nn
#define KP 72         // bf16 row stride for h and weight tiles
#define XP 68         // fp32 row stride for xl/xr
#define OP 68         // fp32 row stride for hOut
#define NTHREADS 512

// ---- block-invariant precomputed state ----
__device__ __align__(16) __nv_bfloat16 g_w[2][2][2][Cc * KP]; // [layer][hi/lo][mat][co*KP+ci]
__device__ __align__(16) float g_vec[2][5 * Cc];              // [layer][bl|br|We|att|bo]
__device__ __align__(16) int4  g_edge[Ee];                    // {src*XP, dst*XP, ew_bits, 0}
__device__ __align__(16) int2  g_csr[Ee];                     // {e, src*XP}
__device__ int g_deg[Nn], g_off[Nn];

struct __align__(16) Smem {
    __nv_bfloat16 hhi[Mm * KP];
    __nv_bfloat16 hlo[Mm * KP];
    union {
        __nv_bfloat16 w[2][2][Cc * KP];   // [hi/lo][mat]
        float hOut[NG][Nn * OP];          // final-layer fp32 result (aliased)
    };
    float xl[NG][Nn * XP];
    float xr[NG][Nn * XP];
    float sc[NG][Ee][Hh];                 // unnormalized exp(score)
    float vecs[5 * Cc] __attribute__((aligned(16)));
    int4  edgePack[Ee];
    int2  csrPack[Ee];
    int   deg[Nn], off[Nn];
};

__global__ void __launch_bounds__(NTHREADS)
gat_setup(const int* __restrict__ ei, const float* __restrict__ ewg,
          const float* __restrict__ Wl, const float* __restrict__ blg,
          const float* __restrict__ Wr, const float* __restrict__ brg,
          const float* __restrict__ Weg, const float* __restrict__ attg,
          const float* __restrict__ bog)
{
    __shared__ int sdst[Ee], ssrc[Ee];
    __shared__ int sdeg[Nn], soff[Nn];
    const int tid = threadIdx.x;

    for (int t = tid; t < 2 * 2 * Cc * Cc; t += NTHREADS) {
        int layer = t >> 13, mat = (t >> 12) & 1, co = (t >> 6) & 63, ci = t & 63;
        const float* W = (mat ? Wr : Wl) + layer * Cc * Cc;
        float wv = W[co * Cc + ci];
        __nv_bfloat16 hi = __float2bfloat16(wv);
        g_w[layer][0][mat][co * KP + ci] = hi;
        g_w[layer][1][mat][co * KP + ci] = __float2bfloat16(wv - __bfloat162float(hi));
    }
    for (int t = tid; t < 2 * 5 * Cc; t += NTHREADS) {
        int layer = t / (5 * Cc), r = t % (5 * Cc), j = r >> 6, c = r & 63;
        const float* p = (j == 0) ? blg : (j == 1) ? brg : (j == 2) ? Weg : (j == 3) ? attg : bog;
        g_vec[layer][r] = p[layer * Cc + c];
    }
    if (tid < Ee) {
        ssrc[tid] = ei[tid]; sdst[tid] = ei[Ee + tid];
        g_edge[tid] = make_int4(ei[tid] * XP, ei[Ee + tid] * XP,
                                __float_as_int(ewg[tid]), 0);
    }
    if (tid < Nn) sdeg[tid] = 0;
    __syncthreads();
    if (tid < Ee) atomicAdd(&sdeg[sdst[tid]], 1);
    __syncthreads();
    if (tid == 0) {
        int a = 0;
        for (int n = 0; n < Nn; n++) { soff[n] = a; g_off[n] = a; g_deg[n] = sdeg[n]; a += sdeg[n]; }
    }
    __syncthreads();
    if (tid < Ee) {
        int n = sdst[tid], rank = 0;
        for (int e2 = 0; e2 < tid; e2++) rank += (sdst[e2] == n);
        g_csr[soff[n] + rank] = make_int2(tid, ssrc[tid] * XP);
    }
}

__device__ __forceinline__ void mma16816(float* d, const unsigned* a, const unsigned* b) {
    asm volatile(
        "mma.sync.aligned.m16n8k16.row.col.f32.bf16.bf16.f32 "
        "{%0,%1,%2,%3}, {%4,%5,%6,%7}, {%8,%9}, {%0,%1,%2,%3};"
        : "+f"(d[0]), "+f"(d[1]), "+f"(d[2]), "+f"(d[3])
        : "r"(a[0]), "r"(a[1]), "r"(a[2]), "r"(a[3]), "r"(b[0]), "r"(b[1]));
}

__device__ __forceinline__ void ldsm_x4(unsigned* r, unsigned addr) {
    asm volatile("ldmatrix.sync.aligned.m8n8.x4.shared.b16 {%0,%1,%2,%3}, [%4];"
        : "=r"(r[0]), "=r"(r[1]), "=r"(r[2]), "=r"(r[3]) : "r"(addr));
}

__device__ __forceinline__ unsigned cvta_s(const void* p) {
    return (unsigned)__cvta_generic_to_shared(p);
}

__global__ void __launch_bounds__(NTHREADS, 2)
gat_fused(const float* __restrict__ x, float* __restrict__ out)
{
    extern __shared__ char smem_raw[];
    Smem* s = reinterpret_cast<Smem*>(smem_raw);
    const int tid = threadIdx.x;
    const int bk = blockIdx.x / (Ll / NG);
    const int lg = blockIdx.x % (Ll / NG);
    const int b  = bk >> 4;
    const int k  = bk & 15;
    const int l0 = lg * NG;

    // ---- load h and convert to bf16 hi/lo ----
    const float* xb = x + ((size_t)b * Cc * Nn) * (Kk * Ll) + (size_t)k * Ll + l0;
    for (int i2 = tid; i2 < Cc * Nn; i2 += NTHREADS) {
        int c = i2 >> 5, n = i2 & 31;
        float2 v = *reinterpret_cast<const float2*>(xb + ((size_t)c * Nn + n) * (Kk * Ll));
        float vv[2] = {v.x, v.y};
        #pragma unroll
        for (int gp = 0; gp < NG; gp++) {
            int o = (gp * Nn + n) * KP + c;
            __nv_bfloat16 hi = __float2bfloat16(vv[gp]);
            s->hhi[o] = hi;
            s->hlo[o] = __float2bfloat16(vv[gp] - __bfloat162float(hi));
        }
    }
    for (int e = tid; e < Ee; e += NTHREADS) {
        s->edgePack[e] = g_edge[e];
        s->csrPack[e]  = g_csr[e];
    }
    if (tid < Nn) { s->deg[tid] = g_deg[tid]; s->off[tid] = g_off[tid]; }

    for (int layer = 0; layer < 2; layer++) {
        __syncthreads();

        // ---- stage weights: bulk contiguous copy ----
        {
            const uint4* wsrc = reinterpret_cast<const uint4*>(g_w[layer]);
            uint4* wdst = reinterpret_cast<uint4*>(s->w);
            #pragma unroll
            for (int t = tid; t < (2 * 2 * Cc * KP * 2) / 16; t += NTHREADS)
                wdst[t] = wsrc[t];
            if (tid < 5 * Cc) s->vecs[tid] = g_vec[layer][tid];
        }
        __syncthreads();

        // ---- tensor-core GEMM via ldmatrix (hi*Whi + hi*Wlo + lo*Whi) ----
        {
            const int w    = tid >> 5;
            const int lane = tid & 31;
            const int gID  = lane >> 2;
            const int tg   = lane & 3;
            const int mat  = w >> 3;           // 0 -> xl, 1 -> xr
            const int mt   = (w >> 1) & 3;
            const int nh   = w & 1;
            const int lr   = lane & 7;
            const int seg  = lane >> 3;
            const int rowA  = mt * 16 + (seg & 1) * 8 + lr;
            const int kOffA = (seg >> 1) * 8;
            const int colB0 = nh * 32 + (seg >> 1) * 8 + lr;
            const int kOffB = (seg & 1) * 8;

            const unsigned hhiB = cvta_s(s->hhi);
            const unsigned hloB = cvta_s(s->hlo);
            const unsigned whiB = cvta_s(s->w[0][mat]);
            const unsigned wloB = cvta_s(s->w[1][mat]);
            const float* bias = s->vecs + mat * Cc;
            float* dst        = mat ? (float*)s->xr : (float*)s->xl;

            float acc[4][4];
            #pragma unroll
            for (int j = 0; j < 4; j++)
                #pragma unroll
                for (int q = 0; q < 4; q++) acc[j][q] = 0.f;

            #pragma unroll
            for (int kk = 0; kk < 4; kk++) {
                const int ka = kk * 16;
                unsigned ah[4], al[4];
                ldsm_x4(ah, hhiB + (unsigned)(rowA * KP + ka + kOffA) * 2);
                ldsm_x4(al, hloB + (unsigned)(rowA * KP + ka + kOffA) * 2);
                #pragma unroll
                for (int jp = 0; jp < 2; jp++) {
                    const int cB = colB0 + jp * 16;
                    unsigned bh[4], blo[4];
                    ldsm_x4(bh,  whiB + (unsigned)(cB * KP + ka + kOffB) * 2);
                    ldsm_x4(blo, wloB + (unsigned)(cB * KP + ka + kOffB) * 2);
                    mma16816(acc[jp * 2],     ah, bh);
                    mma16816(acc[jp * 2],     ah, blo);
                    mma16816(acc[jp * 2],     al, bh);
                    mma16816(acc[jp * 2 + 1], ah, bh + 2);
                    mma16816(acc[jp * 2 + 1], ah, blo + 2);
                    mma16816(acc[jp * 2 + 1], al, bh + 2);
                }
            }
            #pragma unroll
            for (int j = 0; j < 4; j++) {
                const int col = nh * 32 + j * 8 + tg * 2;
                float2 bv = *reinterpret_cast<const float2*>(bias + col);
                int r0 = mt * 16 + gID, r1 = r0 + 8;
                float2 v0 = make_float2(acc[j][0] + bv.x, acc[j][1] + bv.y);
                float2 v1 = make_float2(acc[j][2] + bv.x, acc[j][3] + bv.y);
                *reinterpret_cast<float2*>(dst + (size_t)(r0 >> 5) * (Nn * XP) + (r0 & 31) * XP + col) = v0;
                *reinterpret_cast<float2*>(dst + (size_t)(r1 >> 5) * (Nn * XP) + (r1 & 31) * XP + col) = v1;
            }
        }
        __syncthreads();

        // ---- edge-parallel scores: sc = exp(score), balanced over edges ----
        {
            const int hd   = tid & 3;
            const int slot = tid >> 2;          // 0..127
            const int base = hd * Dd;
            const float* Wes  = s->vecs + 2 * Cc;
            const float* atts = s->vecs + 3 * Cc;
            for (int e = slot; e < Ee; e += 128) {
                int4 ed = s->edgePack[e];
                float w = __int_as_float(ed.z);
                #pragma unroll
                for (int gp = 0; gp < NG; gp++) {
                    const float* xlp = &s->xl[gp][ed.x + base];
                    const float* xrp = &s->xr[gp][ed.y + base];
                    float sum = 0.f;
                    #pragma unroll
                    for (int q = 0; q < 4; q++) {
                        float4 a  = *reinterpret_cast<const float4*>(xlp + q * 4);
                        float4 bq = *reinterpret_cast<const float4*>(xrp + q * 4);
                        float4 wq = *reinterpret_cast<const float4*>(Wes + base + q * 4);
                        float4 tq = *reinterpret_cast<const float4*>(atts + base + q * 4);
                        float z;
                        z = a.x + bq.x + w * wq.x; z = fmaxf(z, 0.2f * z); sum = fmaf(z, tq.x, sum);
                        z = a.y + bq.y + w * wq.y; z = fmaxf(z, 0.2f * z); sum = fmaf(z, tq.y, sum);
                        z = a.z + bq.z + w * wq.z; z = fmaxf(z, 0.2f * z); sum = fmaf(z, tq.z, sum);
                        z = a.w + bq.w + w * wq.w; z = fmaxf(z, 0.2f * z); sum = fmaf(z, tq.w, sum);
                    }
                    s->sc[gp][e][hd] = __expf(sum);
                }
            }
        }
        __syncthreads();

        // ---- aggregate + inline denominator; lane pairs split each node's edges ----
        {
            const int par = tid & 1;
            const int c8  = (tid >> 1) & 7;     // 8-channel group
            const int n   = tid >> 4;           // 0..31
            const int hd  = c8 >> 1;
            const int cb  = c8 * 8;
            const int dg = s->deg[n], o = s->off[n];
            float4 a00 = make_float4(0.f,0.f,0.f,0.f), a01 = a00, a10 = a00, a11 = a00;
            float d0 = 0.f, d1 = 0.f;
            for (int j = par; j < dg; j += 2) {
                int2 ce = s->csrPack[o + j];
                float s0 = s->sc[0][ce.x][hd];
                float s1 = s->sc[1][ce.x][hd];
                const float* p0 = &s->xl[0][ce.y + cb];
                const float* p1 = &s->xl[1][ce.y + cb];
                float4 v00 = *reinterpret_cast<const float4*>(p0);
                float4 v01 = *reinterpret_cast<const float4*>(p0 + 4);
                float4 v10 = *reinterpret_cast<const float4*>(p1);
                float4 v11 = *reinterpret_cast<const float4*>(p1 + 4);
                a00.x = fmaf(s0, v00.x, a00.x); a00.y = fmaf(s0, v00.y, a00.y);
                a00.z = fmaf(s0, v00.z, a00.z); a00.w = fmaf(s0, v00.w, a00.w);
                a01.x = fmaf(s0, v01.x, a01.x); a01.y = fmaf(s0, v01.y, a01.y);
                a01.z = fmaf(s0, v01.z, a01.z); a01.w = fmaf(s0, v01.w, a01.w);
                a10.x = fmaf(s1, v10.x, a10.x); a10.y = fmaf(s1, v10.y, a10.y);
                a10.z = fmaf(s1, v10.z, a10.z); a10.w = fmaf(s1, v10.w, a10.w);
                a11.x = fmaf(s1, v11.x, a11.x); a11.y = fmaf(s1, v11.y, a11.y);
                a11.z = fmaf(s1, v11.z, a11.z); a11.w = fmaf(s1, v11.w, a11.w);
                d0 += s0; d1 += s1;
            }
            // combine lane pair
            #define CMB(f) f += __shfl_xor_sync(0xffffffffu, f, 1)
            CMB(a00.x); CMB(a00.y); CMB(a00.z); CMB(a00.w);
            CMB(a01.x); CMB(a01.y); CMB(a01.z); CMB(a01.w);
            CMB(a10.x); CMB(a10.y); CMB(a10.z); CMB(a10.w);
            CMB(a11.x); CMB(a11.y); CMB(a11.z); CMB(a11.w);
            CMB(d0); CMB(d1);
            #undef CMB
            if (par == 0) {
                float r0 = (d0 > 0.f) ? (1.f / d0) : 0.f;
                float r1 = (d1 > 0.f) ? (1.f / d1) : 0.f;
                float4 b0 = *reinterpret_cast<const float4*>(s->vecs + 4 * Cc + cb);
                float4 b1 = *reinterpret_cast<const float4*>(s->vecs + 4 * Cc + cb + 4);
                float v0[8] = { fmaf(a00.x, r0, b0.x), fmaf(a00.y, r0, b0.y),
                                fmaf(a00.z, r0, b0.z), fmaf(a00.w, r0, b0.w),
                                fmaf(a01.x, r0, b1.x), fmaf(a01.y, r0, b1.y),
                                fmaf(a01.z, r0, b1.z), fmaf(a01.w, r0, b1.w) };
                float v1[8] = { fmaf(a10.x, r1, b0.x), fmaf(a10.y, r1, b0.y),
                                fmaf(a10.z, r1, b0.z), fmaf(a10.w, r1, b0.w),
                                fmaf(a11.x, r1, b1.x), fmaf(a11.y, r1, b1.y),
                                fmaf(a11.z, r1, b1.z), fmaf(a11.w, r1, b1.w) };
                if (layer == 0) {
                    int o0 = n * KP + cb, o1 = (Nn + n) * KP + cb;
                    #pragma unroll
                    for (int q = 0; q < 8; q++) {
                        float f0 = fmaxf(v0[q], 0.f), f1 = fmaxf(v1[q], 0.f);
                        __nv_bfloat16 h0 = __float2bfloat16(f0);
                        __nv_bfloat16 h1 = __float2bfloat16(f1);
                        s->hhi[o0 + q] = h0;
                        s->hlo[o0 + q] = __float2bfloat16(f0 - __bfloat162float(h0));
                        s->hhi[o1 + q] = h1;
                        s->hlo[o1 + q] = __float2bfloat16(f1 - __bfloat162float(h1));
                    }
                } else {
                    float* q0 = &s->hOut[0][n * OP + cb];
                    float* q1 = &s->hOut[1][n * OP + cb];
                    *reinterpret_cast<float4*>(q0)     = make_float4(v0[0], v0[1], v0[2], v0[3]);
                    *reinterpret_cast<float4*>(q0 + 4) = make_float4(v0[4], v0[5], v0[6], v0[7]);
                    *reinterpret_cast<float4*>(q1)     = make_float4(v1[0], v1[1], v1[2], v1[3]);
                    *reinterpret_cast<float4*>(q1 + 4) = make_float4(v1[4], v1[5], v1[6], v1[7]);
                }
            }
        }
    }
    __syncthreads();

    // ---- write output ----
    float* ob = out + ((size_t)b * Cc * Nn) * (Kk * Ll) + (size_t)k * Ll + l0;
    for (int i2 = tid; i2 < Cc * Nn; i2 += NTHREADS) {
        int c = i2 >> 5, n = i2 & 31;
        float2 v = make_float2(s->hOut[0][n * OP + c], s->hOut[1][n * OP + c]);
        *reinterpret_cast<float2*>(ob + ((size_t)c * Nn + n) * (Kk * Ll)) = v;
    }
}

extern "C" void kernel_launch(void* const* d_in, const int* in_sizes, int n_in,
                              void* d_out, int out_size)
{
    const float* x   = (const float*)d_in[0];
    const int*   ei  = (const int*)  d_in[1];
    const float* ewg = (const float*)d_in[2];
    const float* Wl  = (const float*)d_in[3];
    const float* bl  = (const float*)d_in[4];
    const float* Wr  = (const float*)d_in[5];
    const float* br  = (const float*)d_in[6];
    const float* We  = (const float*)d_in[7];
    const float* att = (const float*)d_in[8];
    const float* bo  = (const float*)d_in[9];
    float* out = (float*)d_out;

    (void)in_sizes; (void)n_in; (void)out_size;

    gat_setup<<<1, NTHREADS>>>(ei, ewg, Wl, bl, Wr, br, We, att, bo);

    int smem = (int)sizeof(Smem);
    cudaFuncSetAttribute(gat_fused, cudaFuncAttributeMaxDynamicSharedMemorySize, smem);
    dim3 grid(Bb * Kk * (Ll / NG));   // 3072 blocks, 2 graphs each
    gat_fused<<<grid, NTHREADS, smem>>>(x, out);
}

// round 8
// speedup vs baseline: 1.1706x; 1.1706x over previous
#include <cuda_runtime.h>
#include <cuda_bf16.h>

// SpatialGNN: 2-layer GATv2, G = 6144 graphs, N=32, C=64, H=4, D=16, E=160.
// R8 = R6 structure (dst-parallel edge phase with register-cached xr/We/att,
// ldmatrix tensor-core GEMM, float4 agg) + inline exp & denominator in the
// edge phase (no max subtraction -- shift-invariant, scores are tiny), which
// deletes the whole softmax pass. csr entries packed as int2.

#define Bb 16
#define Cc 64
#define Nn 32
#define Kk 16
#define Ll 24
#define Ee 160
#define Hh 4
#define Dd 16
#define NG 2
#define Mm 64         // GEMM rows = NG * Nn
#define KP 72         // bf16 row stride for h and weight tiles
#define XP 68         // fp32 row stride for xl/xr
#define OP 68         // fp32 row stride for hOut
#define NTHREADS 512

// ---- block-invariant precomputed state ----
__device__ __align__(16) __nv_bfloat16 g_w[2][2][2][Cc * KP]; // [layer][hi/lo][mat][co*KP+ci]
__device__ __align__(16) float g_vec[2][5 * Cc];              // [layer][bl|br|We|att|bo]
__device__ __align__(16) int2  g_csr[Ee];                     // {e, src*XP} grouped by dst
__device__ __align__(16) float g_csrw[Ee];                    // edge weight, same order
__device__ int g_deg[Nn], g_off[Nn];

struct __align__(16) Smem {
    __nv_bfloat16 hhi[Mm * KP];
    __nv_bfloat16 hlo[Mm * KP];
    union {
        __nv_bfloat16 w[2][2][Cc * KP];   // [hi/lo][mat]
        float hOut[NG][Nn * OP];          // final-layer fp32 result (aliased)
    };
    float xl[NG][Nn * XP];
    float xr[NG][Nn * XP];
    float sc[NG][Ee][Hh];                 // unnormalized exp(score)
    float rden[NG][Nn][Hh];
    float vecs[5 * Cc] __attribute__((aligned(16)));
    int2  csrPack[Ee];
    float csrW[Ee];
    int   deg[Nn], off[Nn];
};

__global__ void __launch_bounds__(NTHREADS)
gat_setup(const int* __restrict__ ei, const float* __restrict__ ewg,
          const float* __restrict__ Wl, const float* __restrict__ blg,
          const float* __restrict__ Wr, const float* __restrict__ brg,
          const float* __restrict__ Weg, const float* __restrict__ attg,
          const float* __restrict__ bog)
{
    __shared__ int sdst[Ee], ssrc[Ee];
    __shared__ float sew[Ee];
    __shared__ int sdeg[Nn], soff[Nn];
    const int tid = threadIdx.x;

    for (int t = tid; t < 2 * 2 * Cc * Cc; t += NTHREADS) {
        int layer = t >> 13, mat = (t >> 12) & 1, co = (t >> 6) & 63, ci = t & 63;
        const float* W = (mat ? Wr : Wl) + layer * Cc * Cc;
        float wv = W[co * Cc + ci];
        __nv_bfloat16 hi = __float2bfloat16(wv);
        g_w[layer][0][mat][co * KP + ci] = hi;
        g_w[layer][1][mat][co * KP + ci] = __float2bfloat16(wv - __bfloat162float(hi));
    }
    for (int t = tid; t < 2 * 5 * Cc; t += NTHREADS) {
        int layer = t / (5 * Cc), r = t % (5 * Cc), j = r >> 6, c = r & 63;
        const float* p = (j == 0) ? blg : (j == 1) ? brg : (j == 2) ? Weg : (j == 3) ? attg : bog;
        g_vec[layer][r] = p[layer * Cc + c];
    }
    if (tid < Ee) { ssrc[tid] = ei[tid]; sdst[tid] = ei[Ee + tid]; sew[tid] = ewg[tid]; }
    if (tid < Nn) sdeg[tid] = 0;
    __syncthreads();
    if (tid < Ee) atomicAdd(&sdeg[sdst[tid]], 1);
    __syncthreads();
    if (tid == 0) {
        int a = 0;
        for (int n = 0; n < Nn; n++) { soff[n] = a; g_off[n] = a; g_deg[n] = sdeg[n]; a += sdeg[n]; }
    }
    __syncthreads();
    if (tid < Ee) {
        int n = sdst[tid], rank = 0;
        for (int e2 = 0; e2 < tid; e2++) rank += (sdst[e2] == n);
        g_csr[soff[n] + rank]  = make_int2(tid, ssrc[tid] * XP);
        g_csrw[soff[n] + rank] = sew[tid];
    }
}

__device__ __forceinline__ void mma16816(float* d, const unsigned* a, const unsigned* b) {
    asm volatile(
        "mma.sync.aligned.m16n8k16.row.col.f32.bf16.bf16.f32 "
        "{%0,%1,%2,%3}, {%4,%5,%6,%7}, {%8,%9}, {%0,%1,%2,%3};"
        : "+f"(d[0]), "+f"(d[1]), "+f"(d[2]), "+f"(d[3])
        : "r"(a[0]), "r"(a[1]), "r"(a[2]), "r"(a[3]), "r"(b[0]), "r"(b[1]));
}

__device__ __forceinline__ void ldsm_x4(unsigned* r, unsigned addr) {
    asm volatile("ldmatrix.sync.aligned.m8n8.x4.shared.b16 {%0,%1,%2,%3}, [%4];"
        : "=r"(r[0]), "=r"(r[1]), "=r"(r[2]), "=r"(r[3]) : "r"(addr));
}

__device__ __forceinline__ unsigned cvta_s(const void* p) {
    return (unsigned)__cvta_generic_to_shared(p);
}

__global__ void __launch_bounds__(NTHREADS, 2)
gat_fused(const float* __restrict__ x, float* __restrict__ out)
{
    extern __shared__ char smem_raw[];
    Smem* s = reinterpret_cast<Smem*>(smem_raw);
    const int tid = threadIdx.x;
    const int bk = blockIdx.x / (Ll / NG);
    const int lg = blockIdx.x % (Ll / NG);
    const int b  = bk >> 4;
    const int k  = bk & 15;
    const int l0 = lg * NG;

    // ---- load h and convert to bf16 hi/lo ----
    const float* xb = x + ((size_t)b * Cc * Nn) * (Kk * Ll) + (size_t)k * Ll + l0;
    for (int i2 = tid; i2 < Cc * Nn; i2 += NTHREADS) {
        int c = i2 >> 5, n = i2 & 31;
        float2 v = *reinterpret_cast<const float2*>(xb + ((size_t)c * Nn + n) * (Kk * Ll));
        float vv[2] = {v.x, v.y};
        #pragma unroll
        for (int gp = 0; gp < NG; gp++) {
            int o = (gp * Nn + n) * KP + c;
            __nv_bfloat16 hi = __float2bfloat16(vv[gp]);
            s->hhi[o] = hi;
            s->hlo[o] = __float2bfloat16(vv[gp] - __bfloat162float(hi));
        }
    }
    for (int e = tid; e < Ee; e += NTHREADS) {
        s->csrPack[e] = g_csr[e];
        s->csrW[e]    = g_csrw[e];
    }
    if (tid < Nn) { s->deg[tid] = g_deg[tid]; s->off[tid] = g_off[tid]; }

    for (int layer = 0; layer < 2; layer++) {
        __syncthreads();

        // ---- stage weights: bulk contiguous copy ----
        {
            const uint4* wsrc = reinterpret_cast<const uint4*>(g_w[layer]);
            uint4* wdst = reinterpret_cast<uint4*>(s->w);
            #pragma unroll
            for (int t = tid; t < (2 * 2 * Cc * KP * 2) / 16; t += NTHREADS)
                wdst[t] = wsrc[t];
            if (tid < 5 * Cc) s->vecs[tid] = g_vec[layer][tid];
        }
        __syncthreads();

        // ---- tensor-core GEMM via ldmatrix (hi*Whi + hi*Wlo + lo*Whi) ----
        {
            const int w    = tid >> 5;
            const int lane = tid & 31;
            const int gID  = lane >> 2;
            const int tg   = lane & 3;
            const int mat  = w >> 3;           // 0 -> xl, 1 -> xr
            const int mt   = (w >> 1) & 3;
            const int nh   = w & 1;
            const int lr   = lane & 7;
            const int seg  = lane >> 3;
            const int rowA  = mt * 16 + (seg & 1) * 8 + lr;
            const int kOffA = (seg >> 1) * 8;
            const int colB0 = nh * 32 + (seg >> 1) * 8 + lr;
            const int kOffB = (seg & 1) * 8;

            const unsigned hhiB = cvta_s(s->hhi);
            const unsigned hloB = cvta_s(s->hlo);
            const unsigned whiB = cvta_s(s->w[0][mat]);
            const unsigned wloB = cvta_s(s->w[1][mat]);
            const float* bias = s->vecs + mat * Cc;
            float* dst        = mat ? (float*)s->xr : (float*)s->xl;

            float acc[4][4];
            #pragma unroll
            for (int j = 0; j < 4; j++)
                #pragma unroll
                for (int q = 0; q < 4; q++) acc[j][q] = 0.f;

            #pragma unroll
            for (int kk = 0; kk < 4; kk++) {
                const int ka = kk * 16;
                unsigned ah[4], al[4];
                ldsm_x4(ah, hhiB + (unsigned)(rowA * KP + ka + kOffA) * 2);
                ldsm_x4(al, hloB + (unsigned)(rowA * KP + ka + kOffA) * 2);
                #pragma unroll
                for (int jp = 0; jp < 2; jp++) {
                    const int cB = colB0 + jp * 16;
                    unsigned bh[4], blo[4];
                    ldsm_x4(bh,  whiB + (unsigned)(cB * KP + ka + kOffB) * 2);
                    ldsm_x4(blo, wloB + (unsigned)(cB * KP + ka + kOffB) * 2);
                    mma16816(acc[jp * 2],     ah, bh);
                    mma16816(acc[jp * 2],     ah, blo);
                    mma16816(acc[jp * 2],     al, bh);
                    mma16816(acc[jp * 2 + 1], ah, bh + 2);
                    mma16816(acc[jp * 2 + 1], ah, blo + 2);
                    mma16816(acc[jp * 2 + 1], al, bh + 2);
                }
            }
            #pragma unroll
            for (int j = 0; j < 4; j++) {
                const int col = nh * 32 + j * 8 + tg * 2;
                float2 bv = *reinterpret_cast<const float2*>(bias + col);
                int r0 = mt * 16 + gID, r1 = r0 + 8;
                float2 v0 = make_float2(acc[j][0] + bv.x, acc[j][1] + bv.y);
                float2 v1 = make_float2(acc[j][2] + bv.x, acc[j][3] + bv.y);
                *reinterpret_cast<float2*>(dst + (size_t)(r0 >> 5) * (Nn * XP) + (r0 & 31) * XP + col) = v0;
                *reinterpret_cast<float2*>(dst + (size_t)(r1 >> 5) * (Nn * XP) + (r1 & 31) * XP + col) = v1;
            }
        }
        __syncthreads();

        // ---- edge scores + inline exp + inline denominator (no max shift) ----
        {
            const int lane = tid & 31;
            const int hf = tid & 1;
            const int hd = (tid >> 1) & 3;
            const int n  = (tid >> 3) & 31;
            const int gp = tid >> 8;
            const int base = hd * Dd + hf * 8;
            const float* Wes  = s->vecs + 2 * Cc;
            const float* atts = s->vecs + 3 * Cc;
            float4 we0 = *reinterpret_cast<const float4*>(Wes + base);
            float4 we1 = *reinterpret_cast<const float4*>(Wes + base + 4);
            float4 at0 = *reinterpret_cast<const float4*>(atts + base);
            float4 at1 = *reinterpret_cast<const float4*>(atts + base + 4);
            float4 xr0 = *reinterpret_cast<const float4*>(&s->xr[gp][n * XP + base]);
            float4 xr1 = *reinterpret_cast<const float4*>(&s->xr[gp][n * XP + base + 4]);
            const int dg = s->deg[n], o = s->off[n];
            const unsigned pmask = 3u << (lane & 30);
            float den = 0.f;
            for (int j = 0; j < dg; j++) {
                int2 ce = s->csrPack[o + j];
                float w = s->csrW[o + j];
                const float* xlp = &s->xl[gp][ce.y];
                float4 a0 = *reinterpret_cast<const float4*>(xlp + base);
                float4 a1 = *reinterpret_cast<const float4*>(xlp + base + 4);
                float z, sum = 0.f;
                z = a0.x + xr0.x + w * we0.x; z = fmaxf(z, 0.2f * z); sum = fmaf(z, at0.x, sum);
                z = a0.y + xr0.y + w * we0.y; z = fmaxf(z, 0.2f * z); sum = fmaf(z, at0.y, sum);
                z = a0.z + xr0.z + w * we0.z; z = fmaxf(z, 0.2f * z); sum = fmaf(z, at0.z, sum);
                z = a0.w + xr0.w + w * we0.w; z = fmaxf(z, 0.2f * z); sum = fmaf(z, at0.w, sum);
                z = a1.x + xr1.x + w * we1.x; z = fmaxf(z, 0.2f * z); sum = fmaf(z, at1.x, sum);
                z = a1.y + xr1.y + w * we1.y; z = fmaxf(z, 0.2f * z); sum = fmaf(z, at1.y, sum);
                z = a1.z + xr1.z + w * we1.z; z = fmaxf(z, 0.2f * z); sum = fmaf(z, at1.z, sum);
                z = a1.w + xr1.w + w * we1.w; z = fmaxf(z, 0.2f * z); sum = fmaf(z, at1.w, sum);
                float full = sum + __shfl_xor_sync(pmask, sum, 1);
                if (hf == 0) {
                    float ex = __expf(full);
                    s->sc[gp][ce.x][hd] = ex;
                    den += ex;
                }
            }
            if (hf == 0)
                s->rden[gp][n][hd] = (dg > 0) ? (1.f / den) : 0.f;
        }
        __syncthreads();

        // ---- aggregate (float4 over channels; both graphs per deg iteration) ----
        {
            const int c4 = tid & 15;          // 4-channel group 0..15
            const int n  = tid >> 4;          // node 0..31
            const int hd = c4 >> 2;
            const int cb = c4 * 4;
            const int dg = s->deg[n], o = s->off[n];
            float4 a0 = make_float4(0.f, 0.f, 0.f, 0.f);
            float4 a1 = make_float4(0.f, 0.f, 0.f, 0.f);
            for (int j = 0; j < dg; j++) {
                int2 ce = s->csrPack[o + j];
                float s0 = s->sc[0][ce.x][hd];
                float s1 = s->sc[1][ce.x][hd];
                float4 v0 = *reinterpret_cast<const float4*>(&s->xl[0][ce.y + cb]);
                float4 v1 = *reinterpret_cast<const float4*>(&s->xl[1][ce.y + cb]);
                a0.x = fmaf(s0, v0.x, a0.x); a0.y = fmaf(s0, v0.y, a0.y);
                a0.z = fmaf(s0, v0.z, a0.z); a0.w = fmaf(s0, v0.w, a0.w);
                a1.x = fmaf(s1, v1.x, a1.x); a1.y = fmaf(s1, v1.y, a1.y);
                a1.z = fmaf(s1, v1.z, a1.z); a1.w = fmaf(s1, v1.w, a1.w);
            }
            float r0 = s->rden[0][n][hd], r1 = s->rden[1][n][hd];
            float4 bo4 = *reinterpret_cast<const float4*>(s->vecs + 4 * Cc + cb);
            a0.x = fmaf(a0.x, r0, bo4.x); a0.y = fmaf(a0.y, r0, bo4.y);
            a0.z = fmaf(a0.z, r0, bo4.z); a0.w = fmaf(a0.w, r0, bo4.w);
            a1.x = fmaf(a1.x, r1, bo4.x); a1.y = fmaf(a1.y, r1, bo4.y);
            a1.z = fmaf(a1.z, r1, bo4.z); a1.w = fmaf(a1.w, r1, bo4.w);
            if (layer == 0) {
                float v0[4] = {fmaxf(a0.x, 0.f), fmaxf(a0.y, 0.f), fmaxf(a0.z, 0.f), fmaxf(a0.w, 0.f)};
                float v1[4] = {fmaxf(a1.x, 0.f), fmaxf(a1.y, 0.f), fmaxf(a1.z, 0.f), fmaxf(a1.w, 0.f)};
                int o0 = n * KP + cb, o1 = (Nn + n) * KP + cb;
                #pragma unroll
                for (int q = 0; q < 4; q++) {
                    __nv_bfloat16 h0 = __float2bfloat16(v0[q]);
                    __nv_bfloat16 h1 = __float2bfloat16(v1[q]);
                    s->hhi[o0 + q] = h0;
                    s->hlo[o0 + q] = __float2bfloat16(v0[q] - __bfloat162float(h0));
                    s->hhi[o1 + q] = h1;
                    s->hlo[o1 + q] = __float2bfloat16(v1[q] - __bfloat162float(h1));
                }
            } else {
                *reinterpret_cast<float4*>(&s->hOut[0][n * OP + cb]) = a0;
                *reinterpret_cast<float4*>(&s->hOut[1][n * OP + cb]) = a1;
            }
        }
    }
    __syncthreads();

    // ---- write output ----
    float* ob = out + ((size_t)b * Cc * Nn) * (Kk * Ll) + (size_t)k * Ll + l0;
    for (int i2 = tid; i2 < Cc * Nn; i2 += NTHREADS) {
        int c = i2 >> 5, n = i2 & 31;
        float2 v = make_float2(s->hOut[0][n * OP + c], s->hOut[1][n * OP + c]);
        *reinterpret_cast<float2*>(ob + ((size_t)c * Nn + n) * (Kk * Ll)) = v;
    }
}

extern "C" void kernel_launch(void* const* d_in, const int* in_sizes, int n_in,
                              void* d_out, int out_size)
{
    const float* x   = (const float*)d_in[0];
    const int*   ei  = (const int*)  d_in[1];
    const float* ewg = (const float*)d_in[2];
    const float* Wl  = (const float*)d_in[3];
    const float* bl  = (const float*)d_in[4];
    const float* Wr  = (const float*)d_in[5];
    const float* br  = (const float*)d_in[6];
    const float* We  = (const float*)d_in[7];
    const float* att = (const float*)d_in[8];
    const float* bo  = (const float*)d_in[9];
    float* out = (float*)d_out;

    (void)in_sizes; (void)n_in; (void)out_size;

    gat_setup<<<1, NTHREADS>>>(ei, ewg, Wl, bl, Wr, br, We, att, bo);

    int smem = (int)sizeof(Smem);
    cudaFuncSetAttribute(gat_fused, cudaFuncAttributeMaxDynamicSharedMemorySize, smem);
    dim3 grid(Bb * Kk * (Ll / NG));   // 3072 blocks, 2 graphs each
    gat_fused<<<grid, NTHREADS, smem>>>(x, out);
}

// round 9
// speedup vs baseline: 1.4048x; 1.2000x over previous
#include <cuda_runtime.h>
#include <cuda_bf16.h>

// SpatialGNN: 2-layer GATv2, G = 6144 graphs, N=32, C=64, H=4, D=16, E=160.
// R9: edge-score loop now ALSO aggregates -- thread (hf,hd,n,gp) accumulates
// acc[8] += exp(score) * xl[src][base..base+8] and den += exp(score) inline
// (the xl values were already loaded for the score dot product). Deletes the
// entire aggregate phase, the sc/rden arrays, and one barrier per layer.

#define Bb 16
#define Cc 64
#define Nn 32
#define Kk 16
#define Ll 24
#define Ee 160
#define Hh 4
#define Dd 16
#define NG 2
#define Mm 64         // GEMM rows = NG * Nn
#define KP 72         // bf16 row stride for h and weight tiles
#define XP 68         // fp32 row stride for xl/xr
#define OP 68         // fp32 row stride for hOut
#define NTHREADS 512

// ---- block-invariant precomputed state ----
__device__ __align__(16) __nv_bfloat16 g_w[2][2][2][Cc * KP]; // [layer][hi/lo][mat][co*KP+ci]
__device__ __align__(16) float g_vec[2][5 * Cc];              // [layer][bl|br|We|att|bo]
__device__ __align__(16) int2  g_csr[Ee];                     // {e, src*XP} grouped by dst
__device__ __align__(16) float g_csrw[Ee];                    // edge weight, same order
__device__ int g_deg[Nn], g_off[Nn];

struct __align__(16) Smem {
    __nv_bfloat16 hhi[Mm * KP];
    __nv_bfloat16 hlo[Mm * KP];
    union {
        __nv_bfloat16 w[2][2][Cc * KP];   // [hi/lo][mat]
        float hOut[NG][Nn * OP];          // final-layer fp32 result (aliased)
    };
    float xl[NG][Nn * XP];
    float xr[NG][Nn * XP];
    float vecs[5 * Cc] __attribute__((aligned(16)));
    int2  csrPack[Ee];
    float csrW[Ee];
    int   deg[Nn], off[Nn];
};

__global__ void __launch_bounds__(NTHREADS)
gat_setup(const int* __restrict__ ei, const float* __restrict__ ewg,
          const float* __restrict__ Wl, const float* __restrict__ blg,
          const float* __restrict__ Wr, const float* __restrict__ brg,
          const float* __restrict__ Weg, const float* __restrict__ attg,
          const float* __restrict__ bog)
{
    __shared__ int sdst[Ee], ssrc[Ee];
    __shared__ float sew[Ee];
    __shared__ int sdeg[Nn], soff[Nn];
    const int tid = threadIdx.x;

    for (int t = tid; t < 2 * 2 * Cc * Cc; t += NTHREADS) {
        int layer = t >> 13, mat = (t >> 12) & 1, co = (t >> 6) & 63, ci = t & 63;
        const float* W = (mat ? Wr : Wl) + layer * Cc * Cc;
        float wv = W[co * Cc + ci];
        __nv_bfloat16 hi = __float2bfloat16(wv);
        g_w[layer][0][mat][co * KP + ci] = hi;
        g_w[layer][1][mat][co * KP + ci] = __float2bfloat16(wv - __bfloat162float(hi));
    }
    for (int t = tid; t < 2 * 5 * Cc; t += NTHREADS) {
        int layer = t / (5 * Cc), r = t % (5 * Cc), j = r >> 6, c = r & 63;
        const float* p = (j == 0) ? blg : (j == 1) ? brg : (j == 2) ? Weg : (j == 3) ? attg : bog;
        g_vec[layer][r] = p[layer * Cc + c];
    }
    if (tid < Ee) { ssrc[tid] = ei[tid]; sdst[tid] = ei[Ee + tid]; sew[tid] = ewg[tid]; }
    if (tid < Nn) sdeg[tid] = 0;
    __syncthreads();
    if (tid < Ee) atomicAdd(&sdeg[sdst[tid]], 1);
    __syncthreads();
    if (tid == 0) {
        int a = 0;
        for (int n = 0; n < Nn; n++) { soff[n] = a; g_off[n] = a; g_deg[n] = sdeg[n]; a += sdeg[n]; }
    }
    __syncthreads();
    if (tid < Ee) {
        int n = sdst[tid], rank = 0;
        for (int e2 = 0; e2 < tid; e2++) rank += (sdst[e2] == n);
        g_csr[soff[n] + rank]  = make_int2(tid, ssrc[tid] * XP);
        g_csrw[soff[n] + rank] = sew[tid];
    }
}

__device__ __forceinline__ void mma16816(float* d, const unsigned* a, const unsigned* b) {
    asm volatile(
        "mma.sync.aligned.m16n8k16.row.col.f32.bf16.bf16.f32 "
        "{%0,%1,%2,%3}, {%4,%5,%6,%7}, {%8,%9}, {%0,%1,%2,%3};"
        : "+f"(d[0]), "+f"(d[1]), "+f"(d[2]), "+f"(d[3])
        : "r"(a[0]), "r"(a[1]), "r"(a[2]), "r"(a[3]), "r"(b[0]), "r"(b[1]));
}

__device__ __forceinline__ void ldsm_x4(unsigned* r, unsigned addr) {
    asm volatile("ldmatrix.sync.aligned.m8n8.x4.shared.b16 {%0,%1,%2,%3}, [%4];"
        : "=r"(r[0]), "=r"(r[1]), "=r"(r[2]), "=r"(r[3]) : "r"(addr));
}

__device__ __forceinline__ unsigned cvta_s(const void* p) {
    return (unsigned)__cvta_generic_to_shared(p);
}

__global__ void __launch_bounds__(NTHREADS, 2)
gat_fused(const float* __restrict__ x, float* __restrict__ out)
{
    extern __shared__ char smem_raw[];
    Smem* s = reinterpret_cast<Smem*>(smem_raw);
    const int tid = threadIdx.x;
    const int bk = blockIdx.x / (Ll / NG);
    const int lg = blockIdx.x % (Ll / NG);
    const int b  = bk >> 4;
    const int k  = bk & 15;
    const int l0 = lg * NG;

    // ---- load h and convert to bf16 hi/lo ----
    const float* xb = x + ((size_t)b * Cc * Nn) * (Kk * Ll) + (size_t)k * Ll + l0;
    for (int i2 = tid; i2 < Cc * Nn; i2 += NTHREADS) {
        int c = i2 >> 5, n = i2 & 31;
        float2 v = *reinterpret_cast<const float2*>(xb + ((size_t)c * Nn + n) * (Kk * Ll));
        float vv[2] = {v.x, v.y};
        #pragma unroll
        for (int gp = 0; gp < NG; gp++) {
            int o = (gp * Nn + n) * KP + c;
            __nv_bfloat16 hi = __float2bfloat16(vv[gp]);
            s->hhi[o] = hi;
            s->hlo[o] = __float2bfloat16(vv[gp] - __bfloat162float(hi));
        }
    }
    for (int e = tid; e < Ee; e += NTHREADS) {
        s->csrPack[e] = g_csr[e];
        s->csrW[e]    = g_csrw[e];
    }
    if (tid < Nn) { s->deg[tid] = g_deg[tid]; s->off[tid] = g_off[tid]; }

    for (int layer = 0; layer < 2; layer++) {
        __syncthreads();

        // ---- stage weights: bulk contiguous copy ----
        {
            const uint4* wsrc = reinterpret_cast<const uint4*>(g_w[layer]);
            uint4* wdst = reinterpret_cast<uint4*>(s->w);
            #pragma unroll
            for (int t = tid; t < (2 * 2 * Cc * KP * 2) / 16; t += NTHREADS)
                wdst[t] = wsrc[t];
            if (tid < 5 * Cc) s->vecs[tid] = g_vec[layer][tid];
        }
        __syncthreads();

        // ---- tensor-core GEMM via ldmatrix (hi*Whi + hi*Wlo + lo*Whi) ----
        {
            const int w    = tid >> 5;
            const int lane = tid & 31;
            const int gID  = lane >> 2;
            const int tg   = lane & 3;
            const int mat  = w >> 3;           // 0 -> xl, 1 -> xr
            const int mt   = (w >> 1) & 3;
            const int nh   = w & 1;
            const int lr   = lane & 7;
            const int seg  = lane >> 3;
            const int rowA  = mt * 16 + (seg & 1) * 8 + lr;
            const int kOffA = (seg >> 1) * 8;
            const int colB0 = nh * 32 + (seg >> 1) * 8 + lr;
            const int kOffB = (seg & 1) * 8;

            const unsigned hhiB = cvta_s(s->hhi);
            const unsigned hloB = cvta_s(s->hlo);
            const unsigned whiB = cvta_s(s->w[0][mat]);
            const unsigned wloB = cvta_s(s->w[1][mat]);
            const float* bias = s->vecs + mat * Cc;
            float* dst        = mat ? (float*)s->xr : (float*)s->xl;

            float acc[4][4];
            #pragma unroll
            for (int j = 0; j < 4; j++)
                #pragma unroll
                for (int q = 0; q < 4; q++) acc[j][q] = 0.f;

            #pragma unroll
            for (int kk = 0; kk < 4; kk++) {
                const int ka = kk * 16;
                unsigned ah[4], al[4];
                ldsm_x4(ah, hhiB + (unsigned)(rowA * KP + ka + kOffA) * 2);
                ldsm_x4(al, hloB + (unsigned)(rowA * KP + ka + kOffA) * 2);
                #pragma unroll
                for (int jp = 0; jp < 2; jp++) {
                    const int cB = colB0 + jp * 16;
                    unsigned bh[4], blo[4];
                    ldsm_x4(bh,  whiB + (unsigned)(cB * KP + ka + kOffB) * 2);
                    ldsm_x4(blo, wloB + (unsigned)(cB * KP + ka + kOffB) * 2);
                    mma16816(acc[jp * 2],     ah, bh);
                    mma16816(acc[jp * 2],     ah, blo);
                    mma16816(acc[jp * 2],     al, bh);
                    mma16816(acc[jp * 2 + 1], ah, bh + 2);
                    mma16816(acc[jp * 2 + 1], ah, blo + 2);
                    mma16816(acc[jp * 2 + 1], al, bh + 2);
                }
            }
            #pragma unroll
            for (int j = 0; j < 4; j++) {
                const int col = nh * 32 + j * 8 + tg * 2;
                float2 bv = *reinterpret_cast<const float2*>(bias + col);
                int r0 = mt * 16 + gID, r1 = r0 + 8;
                float2 v0 = make_float2(acc[j][0] + bv.x, acc[j][1] + bv.y);
                float2 v1 = make_float2(acc[j][2] + bv.x, acc[j][3] + bv.y);
                *reinterpret_cast<float2*>(dst + (size_t)(r0 >> 5) * (Nn * XP) + (r0 & 31) * XP + col) = v0;
                *reinterpret_cast<float2*>(dst + (size_t)(r1 >> 5) * (Nn * XP) + (r1 & 31) * XP + col) = v1;
            }
        }
        __syncthreads();

        // ---- FUSED edge scores + softmax + aggregation ----
        // thread (hf, hd, n, gp) owns channels [hd*16 + hf*8, +8) of node n:
        // per incoming edge it loads xl[src] once, uses it for BOTH the score
        // dot-product and the weighted accumulation.
        {
            const int lane = tid & 31;
            const int hf = tid & 1;
            const int hd = (tid >> 1) & 3;
            const int n  = (tid >> 3) & 31;
            const int gp = tid >> 8;
            const int base = hd * Dd + hf * 8;
            const float* Wes  = s->vecs + 2 * Cc;
            const float* atts = s->vecs + 3 * Cc;
            float4 we0 = *reinterpret_cast<const float4*>(Wes + base);
            float4 we1 = *reinterpret_cast<const float4*>(Wes + base + 4);
            float4 at0 = *reinterpret_cast<const float4*>(atts + base);
            float4 at1 = *reinterpret_cast<const float4*>(atts + base + 4);
            float4 xr0 = *reinterpret_cast<const float4*>(&s->xr[gp][n * XP + base]);
            float4 xr1 = *reinterpret_cast<const float4*>(&s->xr[gp][n * XP + base + 4]);
            const int dg = s->deg[n], o = s->off[n];
            const unsigned pmask = 3u << (lane & 30);
            float4 ac0 = make_float4(0.f, 0.f, 0.f, 0.f);
            float4 ac1 = make_float4(0.f, 0.f, 0.f, 0.f);
            float den = 0.f;
            for (int j = 0; j < dg; j++) {
                int2 ce = s->csrPack[o + j];
                float w = s->csrW[o + j];
                const float* xlp = &s->xl[gp][ce.y];
                float4 a0 = *reinterpret_cast<const float4*>(xlp + base);
                float4 a1 = *reinterpret_cast<const float4*>(xlp + base + 4);
                float z, sum = 0.f;
                z = a0.x + xr0.x + w * we0.x; z = fmaxf(z, 0.2f * z); sum = fmaf(z, at0.x, sum);
                z = a0.y + xr0.y + w * we0.y; z = fmaxf(z, 0.2f * z); sum = fmaf(z, at0.y, sum);
                z = a0.z + xr0.z + w * we0.z; z = fmaxf(z, 0.2f * z); sum = fmaf(z, at0.z, sum);
                z = a0.w + xr0.w + w * we0.w; z = fmaxf(z, 0.2f * z); sum = fmaf(z, at0.w, sum);
                z = a1.x + xr1.x + w * we1.x; z = fmaxf(z, 0.2f * z); sum = fmaf(z, at1.x, sum);
                z = a1.y + xr1.y + w * we1.y; z = fmaxf(z, 0.2f * z); sum = fmaf(z, at1.y, sum);
                z = a1.z + xr1.z + w * we1.z; z = fmaxf(z, 0.2f * z); sum = fmaf(z, at1.z, sum);
                z = a1.w + xr1.w + w * we1.w; z = fmaxf(z, 0.2f * z); sum = fmaf(z, at1.w, sum);
                float ex = __expf(sum + __shfl_xor_sync(pmask, sum, 1));
                den += ex;
                ac0.x = fmaf(ex, a0.x, ac0.x); ac0.y = fmaf(ex, a0.y, ac0.y);
                ac0.z = fmaf(ex, a0.z, ac0.z); ac0.w = fmaf(ex, a0.w, ac0.w);
                ac1.x = fmaf(ex, a1.x, ac1.x); ac1.y = fmaf(ex, a1.y, ac1.y);
                ac1.z = fmaf(ex, a1.z, ac1.z); ac1.w = fmaf(ex, a1.w, ac1.w);
            }
            float r = (dg > 0) ? (1.f / den) : 0.f;
            float4 b0 = *reinterpret_cast<const float4*>(s->vecs + 4 * Cc + base);
            float4 b1 = *reinterpret_cast<const float4*>(s->vecs + 4 * Cc + base + 4);
            float v[8] = { fmaf(ac0.x, r, b0.x), fmaf(ac0.y, r, b0.y),
                           fmaf(ac0.z, r, b0.z), fmaf(ac0.w, r, b0.w),
                           fmaf(ac1.x, r, b1.x), fmaf(ac1.y, r, b1.y),
                           fmaf(ac1.z, r, b1.z), fmaf(ac1.w, r, b1.w) };
            if (layer == 0) {
                int oo = (gp * Nn + n) * KP + base;
                #pragma unroll
                for (int q = 0; q < 8; q++) {
                    float f = fmaxf(v[q], 0.f);
                    __nv_bfloat16 hi = __float2bfloat16(f);
                    s->hhi[oo + q] = hi;
                    s->hlo[oo + q] = __float2bfloat16(f - __bfloat162float(hi));
                }
            } else {
                float* q = &s->hOut[gp][n * OP + base];
                *reinterpret_cast<float4*>(q)     = make_float4(v[0], v[1], v[2], v[3]);
                *reinterpret_cast<float4*>(q + 4) = make_float4(v[4], v[5], v[6], v[7]);
            }
        }
    }
    __syncthreads();

    // ---- write output ----
    float* ob = out + ((size_t)b * Cc * Nn) * (Kk * Ll) + (size_t)k * Ll + l0;
    for (int i2 = tid; i2 < Cc * Nn; i2 += NTHREADS) {
        int c = i2 >> 5, n = i2 & 31;
        float2 v = make_float2(s->hOut[0][n * OP + c], s->hOut[1][n * OP + c]);
        *reinterpret_cast<float2*>(ob + ((size_t)c * Nn + n) * (Kk * Ll)) = v;
    }
}

extern "C" void kernel_launch(void* const* d_in, const int* in_sizes, int n_in,
                              void* d_out, int out_size)
{
    const float* x   = (const float*)d_in[0];
    const int*   ei  = (const int*)  d_in[1];
    const float* ewg = (const float*)d_in[2];
    const float* Wl  = (const float*)d_in[3];
    const float* bl  = (const float*)d_in[4];
    const float* Wr  = (const float*)d_in[5];
    const float* br  = (const float*)d_in[6];
    const float* We  = (const float*)d_in[7];
    const float* att = (const float*)d_in[8];
    const float* bo  = (const float*)d_in[9];
    float* out = (float*)d_out;

    (void)in_sizes; (void)n_in; (void)out_size;

    gat_setup<<<1, NTHREADS>>>(ei, ewg, Wl, bl, Wr, br, We, att, bo);

    int smem = (int)sizeof(Smem);
    cudaFuncSetAttribute(gat_fused, cudaFuncAttributeMaxDynamicSharedMemorySize, smem);
    dim3 grid(Bb * Kk * (Ll / NG));   // 3072 blocks, 2 graphs each
    gat_fused<<<grid, NTHREADS, smem>>>(x, out);
}